// round 3
// baseline (speedup 1.0000x reference)
#include <cuda_runtime.h>

// CosineSimilarity: out[e] = <h[src[e]], h[dst[e]]> / (||h[src[e]]|| * ||h[dst[e]]||)
// N=100000, D=128, E=640000 (sizes taken from in_sizes at runtime; D fixed 128).

#define D_DIM 128
#define MAX_N 100000

// Scratch: per-node inverse L2 norm (400 KB). __device__ global per alloc rules.
__device__ float g_inv_norm[MAX_N];
// Index dtype flag: 1 => int64 indices, 0 => int32 indices.
__device__ int g_idx_is64;

// ---------------------------------------------------------------------------
// Detect index width: if the buffer holds little-endian int64 values < 2^31,
// every odd 32-bit word is zero. For int32 data those words are random indices
// in [0, 100000) — P(zero) ~ 1e-5 each, so 128 samples make this exact in
// practice. Reads only the first 1 KB (buffer is >= 2.56 MB either way).
// ---------------------------------------------------------------------------
__global__ void detect_idx_kernel(const unsigned int* __restrict__ words) {
    int lane = threadIdx.x & 31;
    unsigned int acc = 0u;
    for (int i = lane; i < 128; i += 32)
        acc |= words[2 * i + 1];
    #pragma unroll
    for (int o = 16; o > 0; o >>= 1)
        acc |= __shfl_xor_sync(0xFFFFFFFFu, acc, o);
    if (lane == 0)
        g_idx_is64 = (acc == 0u) ? 1 : 0;
}

// ---------------------------------------------------------------------------
// Pass 1: one warp per node row. 32 lanes x float4 = 128 floats, sum of
// squares, warp reduce, write 1/max(norm, eps).
// ---------------------------------------------------------------------------
__global__ void norm_kernel(const float* __restrict__ h, int N) {
    int gw   = (blockIdx.x * blockDim.x + threadIdx.x) >> 5;
    int lane = threadIdx.x & 31;
    if (gw >= N) return;

    const float4* row = reinterpret_cast<const float4*>(h + (size_t)gw * D_DIM);
    float4 v = __ldg(&row[lane]);
    float ss = v.x * v.x + v.y * v.y + v.z * v.z + v.w * v.w;
    #pragma unroll
    for (int o = 16; o > 0; o >>= 1)
        ss += __shfl_xor_sync(0xFFFFFFFFu, ss, o);

    if (lane == 0) {
        float n = sqrtf(ss);
        g_inv_norm[gw] = 1.0f / fmaxf(n, 1e-12f);
    }
}

// ---------------------------------------------------------------------------
// Pass 2: one warp per edge. Each lane loads one float4 from the src row and
// one from the dst row (2x LDG.128, fully coalesced 512 B per row), partial
// dot, warp reduce, scale by inverse norms.
// ---------------------------------------------------------------------------
__global__ void edge_kernel(const float* __restrict__ h,
                            const void* __restrict__ src_raw,
                            const void* __restrict__ dst_raw,
                            float* __restrict__ out, int E) {
    int gw   = (blockIdx.x * blockDim.x + threadIdx.x) >> 5;
    int lane = threadIdx.x & 31;
    if (gw >= E) return;

    long long s, d;
    if (g_idx_is64) {
        s = __ldg(&reinterpret_cast<const long long*>(src_raw)[gw]);
        d = __ldg(&reinterpret_cast<const long long*>(dst_raw)[gw]);
    } else {
        s = __ldg(&reinterpret_cast<const int*>(src_raw)[gw]);
        d = __ldg(&reinterpret_cast<const int*>(dst_raw)[gw]);
    }

    const float4* rs = reinterpret_cast<const float4*>(h + (size_t)s * D_DIM);
    const float4* rd = reinterpret_cast<const float4*>(h + (size_t)d * D_DIM);
    float4 a = __ldg(&rs[lane]);
    float4 b = __ldg(&rd[lane]);

    float acc = a.x * b.x + a.y * b.y + a.z * b.z + a.w * b.w;
    #pragma unroll
    for (int o = 16; o > 0; o >>= 1)
        acc += __shfl_xor_sync(0xFFFFFFFFu, acc, o);

    if (lane == 0)
        out[gw] = acc * g_inv_norm[s] * g_inv_norm[d];
}

extern "C" void kernel_launch(void* const* d_in, const int* in_sizes, int n_in,
                              void* d_out, int out_size) {
    const float* h   = (const float*)d_in[0];
    const void*  src = d_in[1];
    const void*  dst = d_in[2];
    float*       out = (float*)d_out;

    int N = in_sizes[0] / D_DIM;   // 100000
    int E = in_sizes[1];           // 640000

    detect_idx_kernel<<<1, 32>>>((const unsigned int*)src);

    {
        int threads = 256;
        int warps_needed = N;
        int blocks = (warps_needed * 32 + threads - 1) / threads;
        norm_kernel<<<blocks, threads>>>(h, N);
    }
    {
        int threads = 256;
        int warps_needed = E;
        int blocks = (warps_needed * 32 + threads - 1) / threads;
        edge_kernel<<<blocks, threads>>>(h, src, dst, out, E);
    }
}

// round 7
// speedup vs baseline: 1.6185x; 1.6185x over previous
#include <cuda_runtime.h>
#include <cuda_fp16.h>

// CosineSimilarity: out[e] = <h[src], h[dst]> / (||h[src]|| * ||h[dst]||)
// N=100000, D=128, E=640000.
//
// Strategy: pre-normalize rows into an fp16 table (25.6 MB, L2-resident),
// then gather+dot with fp32 accumulation. Halves the L2 gather traffic vs fp32.

#define D_DIM 128
#define MAX_N 100000

// Normalized feature table, fp16: 100000 * 128 * 2B = 25.6 MB (static scratch).
__device__ __half g_hn[MAX_N * D_DIM];
// Index dtype flag: 1 => int64 indices, 0 => int32 indices.
__device__ int g_idx_is64;

// ---------------------------------------------------------------------------
// Pass 1: one warp per node. Load row (32 x float4), sum of squares, warp
// reduce, broadcast inv_norm, convert to fp16 and store normalized row
// (each lane writes 4 halves = 8 B; 256 B/row coalesced).
// One extra warp past the node range does index-width detection instead:
// int64 values < 2^31 (little-endian) have all odd 32-bit words zero; for
// int32 data those words are random node indices — 128 samples make this exact.
// ---------------------------------------------------------------------------
__global__ void norm_kernel(const float* __restrict__ h,
                            const unsigned int* __restrict__ idx_words, int N) {
    int gw   = (blockIdx.x * blockDim.x + threadIdx.x) >> 5;
    int lane = threadIdx.x & 31;

    if (gw >= N) {
        if (gw == N) {
            unsigned int acc = 0u;
            for (int i = lane; i < 128; i += 32)
                acc |= idx_words[2 * i + 1];
            #pragma unroll
            for (int o = 16; o > 0; o >>= 1)
                acc |= __shfl_xor_sync(0xFFFFFFFFu, acc, o);
            if (lane == 0)
                g_idx_is64 = (acc == 0u) ? 1 : 0;
        }
        return;
    }

    const float4* row = reinterpret_cast<const float4*>(h + (size_t)gw * D_DIM);
    float4 v = __ldg(&row[lane]);
    float ss = v.x * v.x + v.y * v.y + v.z * v.z + v.w * v.w;
    #pragma unroll
    for (int o = 16; o > 0; o >>= 1)
        ss += __shfl_xor_sync(0xFFFFFFFFu, ss, o);

    float inv = 1.0f / fmaxf(sqrtf(ss), 1e-12f);   // uniform across warp

    __half2 h0 = __floats2half2_rn(v.x * inv, v.y * inv);
    __half2 h1 = __floats2half2_rn(v.z * inv, v.w * inv);
    uint2 packed;
    packed.x = *reinterpret_cast<unsigned int*>(&h0);
    packed.y = *reinterpret_cast<unsigned int*>(&h1);
    // row of 128 halves = 32 x uint2 (8 B per lane)
    reinterpret_cast<uint2*>(g_hn + (size_t)gw * D_DIM)[lane] = packed;
}

// ---------------------------------------------------------------------------
// Pass 2: 16 lanes per edge (2 edges per warp). Each lane loads one float4
// (= 8 halves, 16 B) from src row and dst row: 256 B/row fully coalesced.
// fp32 accumulation, 4-step shuffle reduce within the 16-lane group.
// ---------------------------------------------------------------------------
__global__ void edge_kernel(const void* __restrict__ src_raw,
                            const void* __restrict__ dst_raw,
                            float* __restrict__ out, int E) {
    int ge  = (blockIdx.x * blockDim.x + threadIdx.x) >> 4;  // edge id
    int sub = threadIdx.x & 15;
    if (ge >= E) return;

    long long s, d;
    if (g_idx_is64) {
        s = __ldg(&reinterpret_cast<const long long*>(src_raw)[ge]);
        d = __ldg(&reinterpret_cast<const long long*>(dst_raw)[ge]);
    } else {
        s = __ldg(&reinterpret_cast<const int*>(src_raw)[ge]);
        d = __ldg(&reinterpret_cast<const int*>(dst_raw)[ge]);
    }

    const float4* rs = reinterpret_cast<const float4*>(g_hn + (size_t)s * D_DIM);
    const float4* rd = reinterpret_cast<const float4*>(g_hn + (size_t)d * D_DIM);
    float4 a = rs[sub];
    float4 b = rd[sub];

    const __half2* ah = reinterpret_cast<const __half2*>(&a);
    const __half2* bh = reinterpret_cast<const __half2*>(&b);
    float acc = 0.0f;
    #pragma unroll
    for (int i = 0; i < 4; i++) {
        float2 af = __half22float2(ah[i]);
        float2 bf = __half22float2(bh[i]);
        acc = fmaf(af.x, bf.x, acc);
        acc = fmaf(af.y, bf.y, acc);
    }

    #pragma unroll
    for (int o = 8; o > 0; o >>= 1)
        acc += __shfl_xor_sync(0xFFFFFFFFu, acc, o);

    if (sub == 0)
        out[ge] = acc;
}

extern "C" void kernel_launch(void* const* d_in, const int* in_sizes, int n_in,
                              void* d_out, int out_size) {
    const float* h   = (const float*)d_in[0];
    const void*  src = d_in[1];
    const void*  dst = d_in[2];
    float*       out = (float*)d_out;

    int N = in_sizes[0] / D_DIM;   // 100000
    int E = in_sizes[1];           // 640000

    {
        int threads = 256;
        // +1 warp of work for the index-width detection
        int warps_needed = N + 1;
        int blocks = (warps_needed * 32 + threads - 1) / threads;
        norm_kernel<<<blocks, threads>>>(h, (const unsigned int*)src, N);
    }
    {
        int threads = 256;
        long long thr_needed = (long long)E * 16;
        int blocks = (int)((thr_needed + threads - 1) / threads);
        edge_kernel<<<blocks, threads>>>(src, dst, out, E);
    }
}

// round 8
// speedup vs baseline: 2.4009x; 1.4834x over previous
#include <cuda_runtime.h>
#include <cuda_fp16.h>

// CosineSimilarity: out[e] = <h[src], h[dst]> / (||h[src]|| * ||h[dst]||)
// N=100000, D=128, E=640000.
//
// fp16 normalized table (25.6 MB, L2-resident). Edge pass: 8 lanes/edge,
// 4 edges/warp, HFMA2 partial accumulation (<=2 products per fp16 half-lane)
// then fp32 reduction.

#define D_DIM 128
#define MAX_N 100000

__device__ __half g_hn[MAX_N * D_DIM];   // normalized rows, fp16 (25.6 MB)
__device__ int g_idx_is64;               // 1 => int64 indices, 0 => int32

// ---------------------------------------------------------------------------
// Pass 1: one warp per node: sum of squares, warp reduce, write fp16
// normalized row (32 lanes x 8 B, coalesced). One extra warp past N does
// index-width detection: int64 values < 2^31 (LE) have all odd 32-bit words
// zero; for int32 those words are random node ids — 128 samples are exact.
// ---------------------------------------------------------------------------
__global__ void norm_kernel(const float* __restrict__ h,
                            const unsigned int* __restrict__ idx_words, int N) {
    int gw   = (blockIdx.x * blockDim.x + threadIdx.x) >> 5;
    int lane = threadIdx.x & 31;

    if (gw >= N) {
        if (gw == N) {
            unsigned int acc = 0u;
            for (int i = lane; i < 128; i += 32)
                acc |= idx_words[2 * i + 1];
            #pragma unroll
            for (int o = 16; o > 0; o >>= 1)
                acc |= __shfl_xor_sync(0xFFFFFFFFu, acc, o);
            if (lane == 0)
                g_idx_is64 = (acc == 0u) ? 1 : 0;
        }
        return;
    }

    const float4* row = reinterpret_cast<const float4*>(h + (size_t)gw * D_DIM);
    float4 v = __ldg(&row[lane]);
    float ss = v.x * v.x + v.y * v.y + v.z * v.z + v.w * v.w;
    #pragma unroll
    for (int o = 16; o > 0; o >>= 1)
        ss += __shfl_xor_sync(0xFFFFFFFFu, ss, o);

    float inv = 1.0f / fmaxf(sqrtf(ss), 1e-12f);   // uniform across warp

    __half2 h0 = __floats2half2_rn(v.x * inv, v.y * inv);
    __half2 h1 = __floats2half2_rn(v.z * inv, v.w * inv);
    uint2 packed;
    packed.x = *reinterpret_cast<unsigned int*>(&h0);
    packed.y = *reinterpret_cast<unsigned int*>(&h1);
    reinterpret_cast<uint2*>(g_hn + (size_t)gw * D_DIM)[lane] = packed;
}

// ---------------------------------------------------------------------------
// Pass 2: 8 lanes per edge (4 edges per warp). Each lane loads 2 float4
// (32 B = 16 halves) from the src row and the dst row; per 8-lane group each
// LDG.128 covers one contiguous 128 B line of the row.
// Math: 8 HFMA2 into 4 half2 accumulators (each fp16 half-lane accumulates
// only 2 products, |partial| ~ 0.02 -> rounding error ~2e-6), then convert
// to fp32 and tree-reduce. 3-step shuffle reduce across the 8-lane group.
// ---------------------------------------------------------------------------
__global__ void edge_kernel(const void* __restrict__ src_raw,
                            const void* __restrict__ dst_raw,
                            float* __restrict__ out, int E) {
    int ge  = (blockIdx.x * blockDim.x + threadIdx.x) >> 3;  // edge id
    int sub = threadIdx.x & 7;
    if (ge >= E) return;

    long long s, d;
    if (g_idx_is64) {
        s = __ldg(&reinterpret_cast<const long long*>(src_raw)[ge]);
        d = __ldg(&reinterpret_cast<const long long*>(dst_raw)[ge]);
    } else {
        s = __ldg(&reinterpret_cast<const int*>(src_raw)[ge]);
        d = __ldg(&reinterpret_cast<const int*>(dst_raw)[ge]);
    }

    const float4* rs = reinterpret_cast<const float4*>(g_hn + (size_t)s * D_DIM);
    const float4* rd = reinterpret_cast<const float4*>(g_hn + (size_t)d * D_DIM);
    float4 a0 = rs[sub];
    float4 a1 = rs[sub + 8];
    float4 b0 = rd[sub];
    float4 b1 = rd[sub + 8];

    const __half2* A0 = reinterpret_cast<const __half2*>(&a0);
    const __half2* A1 = reinterpret_cast<const __half2*>(&a1);
    const __half2* B0 = reinterpret_cast<const __half2*>(&b0);
    const __half2* B1 = reinterpret_cast<const __half2*>(&b1);

    __half2 z = __floats2half2_rn(0.0f, 0.0f);
    __half2 c0 = z, c1 = z, c2 = z, c3 = z;
    c0 = __hfma2(A0[0], B0[0], c0);  c0 = __hfma2(A1[0], B1[0], c0);
    c1 = __hfma2(A0[1], B0[1], c1);  c1 = __hfma2(A1[1], B1[1], c1);
    c2 = __hfma2(A0[2], B0[2], c2);  c2 = __hfma2(A1[2], B1[2], c2);
    c3 = __hfma2(A0[3], B0[3], c3);  c3 = __hfma2(A1[3], B1[3], c3);

    float2 f0 = __half22float2(c0);
    float2 f1 = __half22float2(c1);
    float2 f2 = __half22float2(c2);
    float2 f3 = __half22float2(c3);
    float acc = ((f0.x + f0.y) + (f1.x + f1.y)) +
                ((f2.x + f2.y) + (f3.x + f3.y));

    #pragma unroll
    for (int o = 4; o > 0; o >>= 1)
        acc += __shfl_xor_sync(0xFFFFFFFFu, acc, o);

    if (sub == 0)
        out[ge] = acc;
}

extern "C" void kernel_launch(void* const* d_in, const int* in_sizes, int n_in,
                              void* d_out, int out_size) {
    const float* h   = (const float*)d_in[0];
    const void*  src = d_in[1];
    const void*  dst = d_in[2];
    float*       out = (float*)d_out;

    int N = in_sizes[0] / D_DIM;   // 100000
    int E = in_sizes[1];           // 640000

    {
        int threads = 256;
        int warps_needed = N + 1;  // +1 warp for index-width detection
        int blocks = (warps_needed * 32 + threads - 1) / threads;
        norm_kernel<<<blocks, threads>>>(h, (const unsigned int*)src, N);
    }
    {
        int threads = 256;
        long long thr_needed = (long long)E * 8;
        int blocks = (int)((thr_needed + threads - 1) / threads);
        edge_kernel<<<blocks, threads>>>(src, dst, out, E);
    }
}

// round 9
// speedup vs baseline: 2.5881x; 1.0780x over previous
#include <cuda_runtime.h>
#include <cuda_fp16.h>

// CosineSimilarity: out[e] = <h[src], h[dst]> / (||h[src]|| * ||h[dst]||)
// N=100000, D=128, E=640000.
//
// fp16 normalized table (25.6 MB, L2-resident). Edge pass: 8 lanes/edge,
// 8 edges/warp (2 per lane-group), all row loads issued up front (MLP=8).
// HFMA2 partial accumulation (<=2 products per fp16 half-lane) + fp32 reduce.

#define D_DIM 128
#define MAX_N 100000

__device__ __half g_hn[MAX_N * D_DIM];   // normalized rows, fp16 (25.6 MB)
__device__ int g_idx_is64;               // 1 => int64 indices, 0 => int32

// ---------------------------------------------------------------------------
// Pass 1: one warp per node: sum of squares, warp reduce, write fp16
// normalized row (32 lanes x 8 B, coalesced). One extra warp past N does
// index-width detection: int64 values < 2^31 (LE) have all odd 32-bit words
// zero; for int32 those words are random node ids — 128 samples are exact.
// ---------------------------------------------------------------------------
__global__ void norm_kernel(const float* __restrict__ h,
                            const unsigned int* __restrict__ idx_words, int N) {
    int gw   = (blockIdx.x * blockDim.x + threadIdx.x) >> 5;
    int lane = threadIdx.x & 31;

    if (gw >= N) {
        if (gw == N) {
            unsigned int acc = 0u;
            for (int i = lane; i < 128; i += 32)
                acc |= idx_words[2 * i + 1];
            #pragma unroll
            for (int o = 16; o > 0; o >>= 1)
                acc |= __shfl_xor_sync(0xFFFFFFFFu, acc, o);
            if (lane == 0)
                g_idx_is64 = (acc == 0u) ? 1 : 0;
        }
        return;
    }

    const float4* row = reinterpret_cast<const float4*>(h + (size_t)gw * D_DIM);
    float4 v = __ldg(&row[lane]);
    float ss = v.x * v.x + v.y * v.y + v.z * v.z + v.w * v.w;
    #pragma unroll
    for (int o = 16; o > 0; o >>= 1)
        ss += __shfl_xor_sync(0xFFFFFFFFu, ss, o);

    float inv = 1.0f / fmaxf(sqrtf(ss), 1e-12f);   // uniform across warp

    __half2 h0 = __floats2half2_rn(v.x * inv, v.y * inv);
    __half2 h1 = __floats2half2_rn(v.z * inv, v.w * inv);
    uint2 packed;
    packed.x = *reinterpret_cast<unsigned int*>(&h0);
    packed.y = *reinterpret_cast<unsigned int*>(&h1);
    reinterpret_cast<uint2*>(g_hn + (size_t)gw * D_DIM)[lane] = packed;
}

// ---------------------------------------------------------------------------
// Per-edge fp16 dot with fp32 finish: 8 HFMA2 into 4 half2 accumulators
// (each fp16 half-lane accumulates only 2 products, |partial| ~ 0.02 ->
// rounding error ~2e-6), convert to fp32 and tree-add.
// ---------------------------------------------------------------------------
__device__ __forceinline__ float dot16(const float4& a0, const float4& a1,
                                       const float4& b0, const float4& b1) {
    const __half2* A0 = reinterpret_cast<const __half2*>(&a0);
    const __half2* A1 = reinterpret_cast<const __half2*>(&a1);
    const __half2* B0 = reinterpret_cast<const __half2*>(&b0);
    const __half2* B1 = reinterpret_cast<const __half2*>(&b1);
    __half2 z = __floats2half2_rn(0.0f, 0.0f);
    __half2 c0 = z, c1 = z, c2 = z, c3 = z;
    c0 = __hfma2(A0[0], B0[0], c0);  c0 = __hfma2(A1[0], B1[0], c0);
    c1 = __hfma2(A0[1], B0[1], c1);  c1 = __hfma2(A1[1], B1[1], c1);
    c2 = __hfma2(A0[2], B0[2], c2);  c2 = __hfma2(A1[2], B1[2], c2);
    c3 = __hfma2(A0[3], B0[3], c3);  c3 = __hfma2(A1[3], B1[3], c3);
    float2 f0 = __half22float2(c0);
    float2 f1 = __half22float2(c1);
    float2 f2 = __half22float2(c2);
    float2 f3 = __half22float2(c3);
    return ((f0.x + f0.y) + (f1.x + f1.y)) +
           ((f2.x + f2.y) + (f3.x + f3.y));
}

// ---------------------------------------------------------------------------
// Pass 2: warp handles 8 edges. Lane-group g (8 lanes) handles edges
// base+g and base+g+4. All 8 row LDG.128 are issued before any math (MLP=8).
// Each 8-lane group's float4 load covers one contiguous 128 B line.
// 32-bit byte offsets into the table (25.6 MB < 4 GB).
// ---------------------------------------------------------------------------
__global__ void edge_kernel(const void* __restrict__ src_raw,
                            const void* __restrict__ dst_raw,
                            float* __restrict__ out, int E) {
    int w    = (blockIdx.x * blockDim.x + threadIdx.x) >> 5;  // warp id
    int lane = threadIdx.x & 31;
    int g    = lane >> 3;
    int sub  = lane & 7;

    int e0 = w * 8 + g;
    int e1 = e0 + 4;
    bool v0 = e0 < E;
    bool v1 = e1 < E;
    if (!v0) return;

    unsigned int s0, d0, s1 = 0, d1 = 0;
    if (g_idx_is64) {
        const long long* S = reinterpret_cast<const long long*>(src_raw);
        const long long* D = reinterpret_cast<const long long*>(dst_raw);
        s0 = (unsigned int)__ldg(&S[e0]);
        d0 = (unsigned int)__ldg(&D[e0]);
        if (v1) { s1 = (unsigned int)__ldg(&S[e1]);
                  d1 = (unsigned int)__ldg(&D[e1]); }
    } else {
        const int* S = reinterpret_cast<const int*>(src_raw);
        const int* D = reinterpret_cast<const int*>(dst_raw);
        s0 = (unsigned int)__ldg(&S[e0]);
        d0 = (unsigned int)__ldg(&D[e0]);
        if (v1) { s1 = (unsigned int)__ldg(&S[e1]);
                  d1 = (unsigned int)__ldg(&D[e1]); }
    }

    const char* base = reinterpret_cast<const char*>(g_hn);
    unsigned int lo = (unsigned int)sub * 16u;          // 0..112 B within line 0
    // row = 256 B; second half-line at +128 B
    const float4* ps0 = reinterpret_cast<const float4*>(base + (s0 << 8) + lo);
    const float4* pd0 = reinterpret_cast<const float4*>(base + (d0 << 8) + lo);
    const float4* ps1 = reinterpret_cast<const float4*>(base + (s1 << 8) + lo);
    const float4* pd1 = reinterpret_cast<const float4*>(base + (d1 << 8) + lo);

    // Issue all row loads up front (independent -> MLP=8 per thread).
    float4 a00 = ps0[0];
    float4 a01 = ps0[8];
    float4 b00 = pd0[0];
    float4 b01 = pd0[8];
    float4 a10, a11, b10, b11;
    if (v1) {
        a10 = ps1[0];
        a11 = ps1[8];
        b10 = pd1[0];
        b11 = pd1[8];
    }

    float acc0 = dot16(a00, a01, b00, b01);
    #pragma unroll
    for (int o = 4; o > 0; o >>= 1)
        acc0 += __shfl_xor_sync(0xFFFFFFFFu, acc0, o);
    if (sub == 0)
        out[e0] = acc0;

    if (v1) {
        float acc1 = dot16(a10, a11, b10, b11);
        #pragma unroll
        for (int o = 4; o > 0; o >>= 1)
            acc1 += __shfl_xor_sync(0xFFFFFFFFu, acc1, o);
        if (sub == 0)
            out[e1] = acc1;
    }
}

extern "C" void kernel_launch(void* const* d_in, const int* in_sizes, int n_in,
                              void* d_out, int out_size) {
    const float* h   = (const float*)d_in[0];
    const void*  src = d_in[1];
    const void*  dst = d_in[2];
    float*       out = (float*)d_out;

    int N = in_sizes[0] / D_DIM;   // 100000
    int E = in_sizes[1];           // 640000

    {
        int threads = 256;
        int warps_needed = N + 1;  // +1 warp for index-width detection
        int blocks = (warps_needed * 32 + threads - 1) / threads;
        norm_kernel<<<blocks, threads>>>(h, (const unsigned int*)src, N);
    }
    {
        int threads = 256;
        // 8 edges per warp
        long long warps_needed = ((long long)E + 7) / 8;
        int blocks = (int)((warps_needed * 32 + threads - 1) / threads);
        edge_kernel<<<blocks, threads>>>(src, dst, out, E);
    }
}

// round 13
// speedup vs baseline: 2.7151x; 1.0491x over previous
#include <cuda_runtime.h>
#include <cuda_fp16.h>

// CosineSimilarity: out[e] = <h[src], h[dst]> / (||h[src]|| * ||h[dst]||)
// N=100000, D=128, E=640000.
//
// fp16 normalized table (25.6 MB, L2-resident). Edge pass: 8 lanes/edge,
// 16 edges/warp (4 consecutive per lane-group), vectorized idx loads,
// all 16 row loads issued up front, STG.128 result stores.

#define D_DIM 128
#define MAX_N 100000

__device__ __half g_hn[MAX_N * D_DIM];   // normalized rows, fp16 (25.6 MB)
__device__ int g_idx_is64;               // 1 => int64 indices, 0 => int32

// ---------------------------------------------------------------------------
// Pass 1: one warp per node: sum of squares, warp reduce, write fp16
// normalized row (32 lanes x 8 B, coalesced). One extra warp past N does
// index-width detection: int64 values < 2^31 (LE) have all odd 32-bit words
// zero; for int32 those words are random node ids — 128 samples are exact.
// ---------------------------------------------------------------------------
__global__ void norm_kernel(const float* __restrict__ h,
                            const unsigned int* __restrict__ idx_words, int N) {
    int gw   = (blockIdx.x * blockDim.x + threadIdx.x) >> 5;
    int lane = threadIdx.x & 31;

    if (gw >= N) {
        if (gw == N) {
            unsigned int acc = 0u;
            for (int i = lane; i < 128; i += 32)
                acc |= idx_words[2 * i + 1];
            #pragma unroll
            for (int o = 16; o > 0; o >>= 1)
                acc |= __shfl_xor_sync(0xFFFFFFFFu, acc, o);
            if (lane == 0)
                g_idx_is64 = (acc == 0u) ? 1 : 0;
        }
        return;
    }

    const float4* row = reinterpret_cast<const float4*>(h + (size_t)gw * D_DIM);
    float4 v = __ldg(&row[lane]);
    float ss = v.x * v.x + v.y * v.y + v.z * v.z + v.w * v.w;
    #pragma unroll
    for (int o = 16; o > 0; o >>= 1)
        ss += __shfl_xor_sync(0xFFFFFFFFu, ss, o);

    float inv = 1.0f / fmaxf(sqrtf(ss), 1e-12f);   // uniform across warp

    __half2 h0 = __floats2half2_rn(v.x * inv, v.y * inv);
    __half2 h1 = __floats2half2_rn(v.z * inv, v.w * inv);
    uint2 packed;
    packed.x = *reinterpret_cast<unsigned int*>(&h0);
    packed.y = *reinterpret_cast<unsigned int*>(&h1);
    reinterpret_cast<uint2*>(g_hn + (size_t)gw * D_DIM)[lane] = packed;
}

// ---------------------------------------------------------------------------
// Per-edge fp16 dot with fp32 finish: 8 HFMA2 into 4 half2 accumulators
// (each fp16 half-lane accumulates only 2 products, |partial| ~ 0.02 ->
// rounding error ~2e-6), convert to fp32 and tree-add.
// ---------------------------------------------------------------------------
__device__ __forceinline__ float dot16(const float4& a0, const float4& a1,
                                       const float4& b0, const float4& b1) {
    const __half2* A0 = reinterpret_cast<const __half2*>(&a0);
    const __half2* A1 = reinterpret_cast<const __half2*>(&a1);
    const __half2* B0 = reinterpret_cast<const __half2*>(&b0);
    const __half2* B1 = reinterpret_cast<const __half2*>(&b1);
    __half2 z = __floats2half2_rn(0.0f, 0.0f);
    __half2 c0 = z, c1 = z, c2 = z, c3 = z;
    c0 = __hfma2(A0[0], B0[0], c0);  c0 = __hfma2(A1[0], B1[0], c0);
    c1 = __hfma2(A0[1], B0[1], c1);  c1 = __hfma2(A1[1], B1[1], c1);
    c2 = __hfma2(A0[2], B0[2], c2);  c2 = __hfma2(A1[2], B1[2], c2);
    c3 = __hfma2(A0[3], B0[3], c3);  c3 = __hfma2(A1[3], B1[3], c3);
    float2 f0 = __half22float2(c0);
    float2 f1 = __half22float2(c1);
    float2 f2 = __half22float2(c2);
    float2 f3 = __half22float2(c3);
    return ((f0.x + f0.y) + (f1.x + f1.y)) +
           ((f2.x + f2.y) + (f3.x + f3.y));
}

// ---------------------------------------------------------------------------
// Pass 2: warp handles 16 edges; lane-group g (8 lanes) handles 4 consecutive
// edges [w*16 + 4g, +4). Indices loaded vectorized (int4 / 2x longlong2),
// all 16 row LDG.128 issued before math (MLP=16/thread), results stored as
// one STG.128 per group. Exit is warp-uniform so full-mask shuffles are safe;
// partial groups take a guarded scalar path (dormant for E % 16 == 0).
// ---------------------------------------------------------------------------
__global__ void edge_kernel(const void* __restrict__ src_raw,
                            const void* __restrict__ dst_raw,
                            float* __restrict__ out, int E) {
    int w    = (blockIdx.x * blockDim.x + threadIdx.x) >> 5;  // warp id
    int lane = threadIdx.x & 31;
    int g    = lane >> 3;
    int sub  = lane & 7;

    if (w * 16 >= E) return;                  // warp-uniform exit
    int ebase = w * 16 + g * 4;
    bool full = (ebase + 4 <= E);             // whole group in range

    unsigned int si[4], di[4];
    if (full) {
        if (g_idx_is64) {
            const longlong2* S = reinterpret_cast<const longlong2*>(src_raw);
            const longlong2* D = reinterpret_cast<const longlong2*>(dst_raw);
            longlong2 s01 = __ldg(&S[ebase >> 1]);
            longlong2 s23 = __ldg(&S[(ebase >> 1) + 1]);
            longlong2 d01 = __ldg(&D[ebase >> 1]);
            longlong2 d23 = __ldg(&D[(ebase >> 1) + 1]);
            si[0] = (unsigned int)s01.x;  si[1] = (unsigned int)s01.y;
            si[2] = (unsigned int)s23.x;  si[3] = (unsigned int)s23.y;
            di[0] = (unsigned int)d01.x;  di[1] = (unsigned int)d01.y;
            di[2] = (unsigned int)d23.x;  di[3] = (unsigned int)d23.y;
        } else {
            int4 sv = __ldg(&reinterpret_cast<const int4*>(src_raw)[ebase >> 2]);
            int4 dv = __ldg(&reinterpret_cast<const int4*>(dst_raw)[ebase >> 2]);
            si[0] = sv.x;  si[1] = sv.y;  si[2] = sv.z;  si[3] = sv.w;
            di[0] = dv.x;  di[1] = dv.y;  di[2] = dv.z;  di[3] = dv.w;
        }
    } else {
        #pragma unroll
        for (int i = 0; i < 4; i++) {
            int e = ebase + i;
            if (e < E) {
                if (g_idx_is64) {
                    si[i] = (unsigned int)__ldg(&reinterpret_cast<const long long*>(src_raw)[e]);
                    di[i] = (unsigned int)__ldg(&reinterpret_cast<const long long*>(dst_raw)[e]);
                } else {
                    si[i] = (unsigned int)__ldg(&reinterpret_cast<const int*>(src_raw)[e]);
                    di[i] = (unsigned int)__ldg(&reinterpret_cast<const int*>(dst_raw)[e]);
                }
            } else {
                si[i] = 0;  di[i] = 0;
            }
        }
    }

    const char* base = reinterpret_cast<const char*>(g_hn);
    unsigned int lo = (unsigned int)sub * 16u;   // 16 B per lane within a line

    // All 16 row loads up front (row = 256 B = two 128 B lines per group).
    float4 a0[4], a1[4], b0[4], b1[4];
    #pragma unroll
    for (int i = 0; i < 4; i++) {
        const float4* ps = reinterpret_cast<const float4*>(base + (si[i] << 8) + lo);
        const float4* pd = reinterpret_cast<const float4*>(base + (di[i] << 8) + lo);
        a0[i] = ps[0];  a1[i] = ps[8];
        b0[i] = pd[0];  b1[i] = pd[8];
    }

    float r[4];
    #pragma unroll
    for (int i = 0; i < 4; i++) {
        float acc = dot16(a0[i], a1[i], b0[i], b1[i]);
        #pragma unroll
        for (int o = 4; o > 0; o >>= 1)
            acc += __shfl_xor_sync(0xFFFFFFFFu, acc, o);
        r[i] = acc;
    }

    if (sub == 0) {
        if (full) {
            *reinterpret_cast<float4*>(out + ebase) =
                make_float4(r[0], r[1], r[2], r[3]);
        } else {
            #pragma unroll
            for (int i = 0; i < 4; i++)
                if (ebase + i < E) out[ebase + i] = r[i];
        }
    }
}

extern "C" void kernel_launch(void* const* d_in, const int* in_sizes, int n_in,
                              void* d_out, int out_size) {
    const float* h   = (const float*)d_in[0];
    const void*  src = d_in[1];
    const void*  dst = d_in[2];
    float*       out = (float*)d_out;

    int N = in_sizes[0] / D_DIM;   // 100000
    int E = in_sizes[1];           // 640000

    {
        int threads = 256;
        int warps_needed = N + 1;  // +1 warp for index-width detection
        int blocks = (warps_needed * 32 + threads - 1) / threads;
        norm_kernel<<<blocks, threads>>>(h, (const unsigned int*)src, N);
    }
    {
        int threads = 128;                       // smaller blocks: better occ at high regs
        long long warps_needed = ((long long)E + 15) / 16;
        int blocks = (int)((warps_needed * 32 + threads - 1) / threads);
        edge_kernel<<<blocks, threads>>>(src, dst, out, E);
    }
}